// round 6
// baseline (speedup 1.0000x reference)
#include <cuda_runtime.h>
#include <cuda_bf16.h>

// ---------------------------------------------------------------------------
// CascadedAttention: B=128, T=75, D=512, V=28
// Kernel 1 (prologue): per-batch GEMM [75,512] @ [512, 512+84+28] -> scratch
//   v3: f32x2 packed FMA (column-pair accumulators), row-chunk tiling
//       (15 rows/block, grid 128x5, 32KB smem, ~5 CTAs/SM -> single wave)
// Kernel 2 (recurrence): 1 CTA per batch row, smem-resident, 75 steps.
//   v3: 640 threads (20 warps), vectorized LDS.128 score loads
// ---------------------------------------------------------------------------

#define B_  128
#define T_  75
#define D_  512
#define V_  28
#define NC  624
#define PT  (T_*NC)          // 46800 floats per batch row

__device__ float g_scr[B_ * PT];   // 23.96 MB static scratch (no allocation)

typedef unsigned long long ull;

__device__ __forceinline__ float ex2f(float x){ float y; asm("ex2.approx.f32 %0, %1;" : "=f"(y) : "f"(x)); return y; }
__device__ __forceinline__ float rcpf(float x){ float y; asm("rcp.approx.f32 %0, %1;" : "=f"(y) : "f"(x)); return y; }
__device__ __forceinline__ float tanhf_hw(float x){ float y; asm("tanh.approx.f32 %0, %1;" : "=f"(y) : "f"(x)); return y; }
#define L2E 1.4426950408889634f
__device__ __forceinline__ float fast_sig(float x){ return fmaf(0.5f, tanhf_hw(0.5f * x), 0.5f); }

// packed f32x2 helpers
__device__ __forceinline__ ull fma2(ull a, ull b, ull c){
    ull d; asm("fma.rn.f32x2 %0, %1, %2, %3;" : "=l"(d) : "l"(a), "l"(b), "l"(c)); return d;
}
__device__ __forceinline__ ull dup2(float x){
    ull d; asm("mov.b64 %0, {%1, %1};" : "=l"(d) : "r"(__float_as_uint(x))); return d;
}

// ---------------------------------------------------------------------------
// Prologue v3.  grid (128, 5): b x row-chunk (15 rows each). 256 threads.
// Thread (tx,ty): rows r0=2ty, r1=2ty+1 (r1==15 is a zero pad row, not stored)
// Col chunks: cc=0: cols[4tx, 4tx+128) of Ua[0:256); cc=1: Ua[256:512);
// then gk(84)+Co(28) on lanes tx<28.
// Accumulators are f32x2 packed over column pairs -> fma.rn.f32x2 (2 MAC/instr)
// ---------------------------------------------------------------------------
__global__ void __launch_bounds__(256, 5)
prologue_kernel(const float* __restrict__ x,
                const float* __restrict__ Ua,
                const float* __restrict__ gk,
                const float* __restrict__ Co,
                const float* __restrict__ Ba2,
                const float* __restrict__ gbias)
{
    __shared__ float xs[16 * D_];           // 32 KB (row 15 zero pad)
    const int b   = blockIdx.x;
    const int rc  = blockIdx.y;
    const int tid = threadIdx.x;
    const int tx  = tid & 31;
    const int ty  = tid >> 5;
    const int row0 = rc * 15;

    // stage 15 rows of x[b]
    const float4* xb = reinterpret_cast<const float4*>(x + (long)b * T_ * D_ + row0 * D_);
    float4* xs4 = reinterpret_cast<float4*>(xs);
    for (int i = tid; i < 15 * (D_/4); i += 256) xs4[i] = xb[i];
    for (int i = tid; i < (D_/4); i += 256) xs4[15 * (D_/4) + i] = make_float4(0.f,0.f,0.f,0.f);
    __syncthreads();

    const int r0 = 2 * ty;
    const int r1 = 2 * ty + 1;
    float* outb = g_scr + (long)b * PT + row0 * NC;

    // ---- Ua, two 256-col chunks ----
    #pragma unroll
    for (int cc = 0; cc < 2; cc++) {
        const int col = cc * 256 + 4 * tx;
        ull acc[2][4];
        {
            ulonglong2 bA = *reinterpret_cast<const ulonglong2*>(&Ba2[col]);
            ulonglong2 bB = *reinterpret_cast<const ulonglong2*>(&Ba2[col + 128]);
            acc[0][0] = bA.x; acc[0][1] = bA.y; acc[0][2] = bB.x; acc[0][3] = bB.y;
            acc[1][0] = bA.x; acc[1][1] = bA.y; acc[1][2] = bB.x; acc[1][3] = bB.y;
        }
        const float* xr0 = &xs[r0 * D_];
        const float* xr1 = &xs[r1 * D_];
        #pragma unroll 4
        for (int k = 0; k < D_; k++) {
            ulonglong2 w0 = *reinterpret_cast<const ulonglong2*>(&Ua[k * D_ + col]);
            ulonglong2 w1 = *reinterpret_cast<const ulonglong2*>(&Ua[k * D_ + col + 128]);
            ull x0 = dup2(xr0[k]);
            ull x1 = dup2(xr1[k]);
            acc[0][0] = fma2(x0, w0.x, acc[0][0]);
            acc[0][1] = fma2(x0, w0.y, acc[0][1]);
            acc[0][2] = fma2(x0, w1.x, acc[0][2]);
            acc[0][3] = fma2(x0, w1.y, acc[0][3]);
            acc[1][0] = fma2(x1, w0.x, acc[1][0]);
            acc[1][1] = fma2(x1, w0.y, acc[1][1]);
            acc[1][2] = fma2(x1, w1.x, acc[1][2]);
            acc[1][3] = fma2(x1, w1.y, acc[1][3]);
        }
        {
            ulonglong2 s;
            s.x = acc[0][0]; s.y = acc[0][1];
            *reinterpret_cast<ulonglong2*>(&outb[r0 * NC + col]) = s;
            s.x = acc[0][2]; s.y = acc[0][3];
            *reinterpret_cast<ulonglong2*>(&outb[r0 * NC + col + 128]) = s;
            if (r1 < 15) {
                s.x = acc[1][0]; s.y = acc[1][1];
                *reinterpret_cast<ulonglong2*>(&outb[r1 * NC + col]) = s;
                s.x = acc[1][2]; s.y = acc[1][3];
                *reinterpret_cast<ulonglong2*>(&outb[r1 * NC + col + 128]) = s;
            }
        }
    }

    // ---- gk (84) + Co (28) on lanes tx<28 ----
    if (tx < 28) {
        const bool isgk  = (tx < 21);
        const float* W   = isgk ? gk : Co;
        const int stride = isgk ? 84 : 28;
        const int col    = isgk ? 4 * tx : 4 * (tx - 21);
        const int ocol   = isgk ? 512 + col : 596 + col;
        ull acc[2][2];
        if (isgk) {
            ulonglong2 bA = *reinterpret_cast<const ulonglong2*>(&gbias[col]);
            acc[0][0] = bA.x; acc[0][1] = bA.y; acc[1][0] = bA.x; acc[1][1] = bA.y;
        } else {
            acc[0][0] = 0ull; acc[0][1] = 0ull; acc[1][0] = 0ull; acc[1][1] = 0ull;
        }
        const float* xr0 = &xs[r0 * D_];
        const float* xr1 = &xs[r1 * D_];
        #pragma unroll 4
        for (int k = 0; k < D_; k++) {
            ulonglong2 w = *reinterpret_cast<const ulonglong2*>(&W[k * stride + col]);
            ull x0 = dup2(xr0[k]);
            ull x1 = dup2(xr1[k]);
            acc[0][0] = fma2(x0, w.x, acc[0][0]);
            acc[0][1] = fma2(x0, w.y, acc[0][1]);
            acc[1][0] = fma2(x1, w.x, acc[1][0]);
            acc[1][1] = fma2(x1, w.y, acc[1][1]);
        }
        ulonglong2 s;
        s.x = acc[0][0]; s.y = acc[0][1];
        *reinterpret_cast<ulonglong2*>(&outb[r0 * NC + ocol]) = s;
        if (r1 < 15) {
            s.x = acc[1][0]; s.y = acc[1][1];
            *reinterpret_cast<ulonglong2*>(&outb[r1 * NC + ocol]) = s;
        }
    }
}

// ---------------------------------------------------------------------------
// Recurrence kernel v3: 128 CTAs x 640 threads (20 warps), 227712 B smem.
// Phase B: lane owns 16 contiguous dims -> 4x LDS.128 per row.
// ---------------------------------------------------------------------------
#define SMEM_FLOATS 56928
#define NTH 640

__global__ void __launch_bounds__(NTH)
recur_kernel(const float* __restrict__ Wa,
             const float* __restrict__ Va,
             const float* __restrict__ Ba1,
             const float* __restrict__ grk,
             const float* __restrict__ gbias,
             const float* __restrict__ Wo,
             const float* __restrict__ Uo,
             const float* __restrict__ Bo,
             const float* __restrict__ emb,
             float* __restrict__ out)
{
    extern __shared__ float smem[];
    float*        uah  = smem;                 // [75][512]
    float*        xgc  = smem + 38400;         // [75][112]
    unsigned int* wab  = reinterpret_cast<unsigned int*>(smem + 46800); // [28][256] bf16x2
    float*        va_s = smem + 53968;
    float*        ba1_s= smem + 54480;
    float*        uo_s = smem + 54992;
    float*        was_s= smem + 55776;
    float*        sc_s = smem + 56288;
    float*        xmc_s= smem + 56448;
    float*        hm_s = smem + 56560;
    float*        st_s = smem + 56648;
    float*        pr_s = smem + 56680;
    float*        woy_s= smem + 56712;
    float*        uoh_s= smem + 56744;
    float*        lut_s= smem + 56776;
    float*        b1_s = smem + 56808;
    float*        bo_s = smem + 56896;

    const int tid  = threadIdx.x;
    const int b    = blockIdx.x;
    const int lane = tid & 31;
    const int wid  = tid >> 5;

    // ---- bulk load precomputed UaH / XGC from scratch ----
    const float4* src = reinterpret_cast<const float4*>(g_scr + (long)b * PT);
    for (int i = tid; i < PT/4; i += NTH) {
        float4 v = src[i];
        int base = i * 4;
        int t = base / NC;
        int c = base - t * NC;
        float* dst = (c < 512) ? &uah[t * 512 + c] : &xgc[t * 112 + (c - 512)];
        *reinterpret_cast<float4*>(dst) = v;
    }
    // ---- params ----
    for (int i = tid; i < 512; i += NTH) { va_s[i] = Va[i]; ba1_s[i] = Ba1[i]; }
    for (int i = tid; i < 784; i += NTH) uo_s[i] = Uo[i];
    for (int i = tid; i < 28*256; i += NTH) {
        int r = i >> 8, c = i & 255;
        __nv_bfloat162 h;
        h.x = __float2bfloat16_rn(Wa[r * 512 + 2*c]);
        h.y = __float2bfloat16_rn(Wa[r * 512 + 2*c + 1]);
        wab[i] = *reinterpret_cast<unsigned int*>(&h);
    }
    if (tid < 84) b1_s[tid] = gbias[84 + tid];
    if (tid < 28) {
        bo_s[tid] = Bo[tid];
        float a = 0.0f;
        #pragma unroll
        for (int j = 0; j < 28; j++) a = fmaf(emb[tid * 28 + j], Wo[j], a);
        lut_s[tid] = a;
    }
    if (tid < 32) { st_s[tid] = 0.0f; pr_s[tid] = 0.0f; }
    __syncthreads();

    // per-lane 16 contiguous dims
    float4 vav0 = *reinterpret_cast<const float4*>(&va_s[lane * 16]);
    float4 vav1 = *reinterpret_cast<const float4*>(&va_s[lane * 16 + 4]);
    float4 vav2 = *reinterpret_cast<const float4*>(&va_s[lane * 16 + 8]);
    float4 vav3 = *reinterpret_cast<const float4*>(&va_s[lane * 16 + 12]);

    float* outb = out + (long)b * T_ * V_;

    for (int t = 0; t < T_; t++) {
        // ---------- Phase A: state-only GEMVs, all in parallel ----------
        if (tid < 256) {
            float2 a = *reinterpret_cast<const float2*>(&ba1_s[2*tid]);
            #pragma unroll
            for (int v = 0; v < 28; v++) {
                float s = st_s[v];
                unsigned int w = wab[v * 256 + tid];
                float wx = __int_as_float(w << 16);
                float wy = __int_as_float(w & 0xffff0000u);
                a.x = fmaf(s, wx, a.x);
                a.y = fmaf(s, wy, a.y);
            }
            *reinterpret_cast<float2*>(&was_s[2*tid]) = a;
        } else if (tid < 340) {
            int g = tid - 256;              // hm: 84 outputs
            float a = b1_s[g];
            #pragma unroll
            for (int v = 0; v < 28; v++) a = fmaf(st_s[v], grk[v * 84 + g], a);
            hm_s[g] = a;
        } else if (wid == 11) {
            if (lane < 28) {                // uoh
                float a = 0.0f;
                #pragma unroll
                for (int u = 0; u < 28; u++) a = fmaf(st_s[u], uo_s[u * 28 + lane], a);
                uoh_s[lane] = a;
            }
        } else if (wid == 12) {
            if (lane < 28) {                // woy (embedding LUT on int(prev_pred))
                int ix = (int)pr_s[lane];
                ix = max(0, min(27, ix));
                woy_s[lane] = lut_s[ix];
            }
        }
        __syncthreads();

        // ---------- Phase B: scores, 20 warps, vectorized loads ----------
        {
            float4 wsv0 = *reinterpret_cast<const float4*>(&was_s[lane * 16]);
            float4 wsv1 = *reinterpret_cast<const float4*>(&was_s[lane * 16 + 4]);
            float4 wsv2 = *reinterpret_cast<const float4*>(&was_s[lane * 16 + 8]);
            float4 wsv3 = *reinterpret_cast<const float4*>(&was_s[lane * 16 + 12]);

            for (int r = wid; r < T_; r += 20) {
                const float4* up = reinterpret_cast<const float4*>(&uah[r * 512 + lane * 16]);
                float4 u0 = up[0], u1 = up[1], u2 = up[2], u3 = up[3];
                float acc0, acc1;
                acc0  = tanhf_hw(u0.x + wsv0.x) * vav0.x;
                acc1  = tanhf_hw(u0.y + wsv0.y) * vav0.y;
                acc0 = fmaf(tanhf_hw(u0.z + wsv0.z), vav0.z, acc0);
                acc1 = fmaf(tanhf_hw(u0.w + wsv0.w), vav0.w, acc1);
                acc0 = fmaf(tanhf_hw(u1.x + wsv1.x), vav1.x, acc0);
                acc1 = fmaf(tanhf_hw(u1.y + wsv1.y), vav1.y, acc1);
                acc0 = fmaf(tanhf_hw(u1.z + wsv1.z), vav1.z, acc0);
                acc1 = fmaf(tanhf_hw(u1.w + wsv1.w), vav1.w, acc1);
                acc0 = fmaf(tanhf_hw(u2.x + wsv2.x), vav2.x, acc0);
                acc1 = fmaf(tanhf_hw(u2.y + wsv2.y), vav2.y, acc1);
                acc0 = fmaf(tanhf_hw(u2.z + wsv2.z), vav2.z, acc0);
                acc1 = fmaf(tanhf_hw(u2.w + wsv2.w), vav2.w, acc1);
                acc0 = fmaf(tanhf_hw(u3.x + wsv3.x), vav3.x, acc0);
                acc1 = fmaf(tanhf_hw(u3.y + wsv3.y), vav3.y, acc1);
                acc0 = fmaf(tanhf_hw(u3.z + wsv3.z), vav3.z, acc0);
                acc1 = fmaf(tanhf_hw(u3.w + wsv3.w), vav3.w, acc1);
                float acc = acc0 + acc1;
                #pragma unroll
                for (int o = 16; o; o >>= 1) acc += __shfl_xor_sync(0xffffffffu, acc, o);
                if (lane == 0) sc_s[r] = acc;
            }
        }
        __syncthreads();

        // ---------- Phase C: softmax-in-registers + sm.XGC (warps 0-3) ----------
        if (wid < 4) {
            float s0 = sc_s[lane];
            float s1 = sc_s[lane + 32];
            float s2 = (lane < 11) ? sc_s[lane + 64] : -3.0e38f;
            float m = fmaxf(fmaxf(s0, s1), s2);
            #pragma unroll
            for (int o = 16; o; o >>= 1) m = fmaxf(m, __shfl_xor_sync(0xffffffffu, m, o));
            float e0 = ex2f((s0 - m) * L2E);
            float e1 = ex2f((s1 - m) * L2E);
            float e2 = (lane < 11) ? ex2f((s2 - m) * L2E) : 0.0f;
            float sum = e0 + e1 + e2;
            #pragma unroll
            for (int o = 16; o; o >>= 1) sum += __shfl_xor_sync(0xffffffffu, sum, o);
            float inv = rcpf(sum);

            int c = wid * 28 + ((lane < 28) ? lane : 0);   // 112 cols; lanes 28-31 duplicate
            float a0 = 0.0f, a1 = 0.0f, a2 = 0.0f, a3 = 0.0f;
            #pragma unroll
            for (int k = 0; k < 75; k += 4) {
                float w0 = __shfl_sync(0xffffffffu, (k      < 32) ? e0 : ((k      < 64) ? e1 : e2), k      & 31);
                a0 = fmaf(w0, xgc[k * 112 + c], a0);
                if (k + 1 < 75) {
                    float w1 = __shfl_sync(0xffffffffu, (k+1 < 32) ? e0 : ((k+1 < 64) ? e1 : e2), (k+1) & 31);
                    a1 = fmaf(w1, xgc[(k+1) * 112 + c], a1);
                }
                if (k + 2 < 75) {
                    float w2 = __shfl_sync(0xffffffffu, (k+2 < 32) ? e0 : ((k+2 < 64) ? e1 : e2), (k+2) & 31);
                    a2 = fmaf(w2, xgc[(k+2) * 112 + c], a2);
                }
                if (k + 3 < 75) {
                    float w3 = __shfl_sync(0xffffffffu, (k+3 < 32) ? e0 : ((k+3 < 64) ? e1 : e2), (k+3) & 31);
                    a3 = fmaf(w3, xgc[(k+3) * 112 + c], a3);
                }
            }
            if (lane < 28) xmc_s[c] = ((a0 + a1) + (a2 + a3)) * inv;
        }
        __syncthreads();

        // ---------- Phase D: GRU gates + output softmax (warp 0) ----------
        if (wid == 0) {
            int v = lane;
            float logit = -3.0e38f;
            float ns = 0.0f;
            if (v < 28) {
                float xz = xmc_s[v],      xr = xmc_s[28 + v], xh  = xmc_s[56 + v];
                float hz = hm_s[v],       hr = hm_s[28 + v],  hh_ = hm_s[56 + v];
                float z  = fast_sig(xz + hz);
                float r  = fast_sig(xr + hr);
                float hh = tanhf_hw(fmaf(r, hh_, xh));
                float st = st_s[v];
                ns = fmaf(z, st - hh, hh);
                logit = ((woy_s[v] + uoh_s[v]) + (xmc_s[84 + v] + bo_s[v]));
            }
            float m = logit;
            #pragma unroll
            for (int o = 16; o; o >>= 1) m = fmaxf(m, __shfl_xor_sync(0xffffffffu, m, o));
            float e = (v < 28) ? ex2f((logit - m) * L2E) : 0.0f;
            float sum = e;
            #pragma unroll
            for (int o = 16; o; o >>= 1) sum += __shfl_xor_sync(0xffffffffu, sum, o);
            float p = e * rcpf(sum);
            if (v < 28) {
                st_s[v] = ns;
                pr_s[v] = p;
                outb[t * V_ + v] = p;
            }
        }
        __syncthreads();
    }
}

// ---------------------------------------------------------------------------
extern "C" void kernel_launch(void* const* d_in, const int* in_sizes, int n_in,
                              void* d_out, int out_size)
{
    const float* x    = (const float*)d_in[0];
    const float* Wa   = (const float*)d_in[1];
    const float* Ua   = (const float*)d_in[2];
    const float* Va   = (const float*)d_in[3];
    const float* Ba1  = (const float*)d_in[4];
    const float* Ba2  = (const float*)d_in[5];
    /* Ba3 (d_in[6]) is softmax-invariant: skipped */
    const float* gk   = (const float*)d_in[7];
    const float* grk  = (const float*)d_in[8];
    const float* gb   = (const float*)d_in[9];
    const float* Wo   = (const float*)d_in[10];
    const float* Uo   = (const float*)d_in[11];
    const float* Co   = (const float*)d_in[12];
    const float* Bo   = (const float*)d_in[13];
    const float* emb  = (const float*)d_in[14];
    float* out = (float*)d_out;

    cudaFuncSetAttribute(recur_kernel, cudaFuncAttributeMaxDynamicSharedMemorySize, SMEM_FLOATS * 4);

    dim3 pg(B_, 5);
    prologue_kernel<<<pg, 256>>>(x, Ua, gk, Co, Ba2, gb);
    recur_kernel<<<B_, NTH, SMEM_FLOATS * 4>>>(Wa, Va, Ba1, grk, gb, Wo, Uo, Bo, emb, out);
}

// round 7
// speedup vs baseline: 1.2411x; 1.2411x over previous
#include <cuda_runtime.h>
#include <cuda_bf16.h>

// ---------------------------------------------------------------------------
// CascadedAttention: B=128, T=75, D=512, V=28
// Kernel 1 (prologue): per-batch GEMM [75,512] @ [512, 512+84+28] -> scratch
//   v4: SCALAR FFMA (f32x2 reverted - sm_100a emulates it), 15-row chunks,
//       grid 128x5, 32KB smem, 5 CTAs/SM -> single balanced wave
// Kernel 2 (recurrence): 1 CTA per batch row, smem-resident, 75 steps.
//   v4 == v2 (R4): 576 thr / 18 warps, conflict-free stride-32 Phase B
//   (v3's lane-contiguous float4 loads caused 16-way LDS bank conflicts)
// ---------------------------------------------------------------------------

#define B_  128
#define T_  75
#define D_  512
#define V_  28
#define NC  624
#define PT  (T_*NC)          // 46800 floats per batch row

__device__ float g_scr[B_ * PT];   // 23.96 MB static scratch (no allocation)

__device__ __forceinline__ float ex2f(float x){ float y; asm("ex2.approx.f32 %0, %1;" : "=f"(y) : "f"(x)); return y; }
__device__ __forceinline__ float rcpf(float x){ float y; asm("rcp.approx.f32 %0, %1;" : "=f"(y) : "f"(x)); return y; }
__device__ __forceinline__ float tanhf_hw(float x){ float y; asm("tanh.approx.f32 %0, %1;" : "=f"(y) : "f"(x)); return y; }
#define L2E 1.4426950408889634f
__device__ __forceinline__ float fast_sig(float x){ return fmaf(0.5f, tanhf_hw(0.5f * x), 0.5f); }

// ---------------------------------------------------------------------------
// Prologue v4. grid (128, 5): b x row-chunk (15 rows). 256 threads = 32tx x 8ty.
// Thread (tx,ty): rows r0=2ty, r1=2ty+1 (row 15 is a zero pad, not stored).
// Main: cols [4tx,4tx+4) and [4tx+128,+4) of each 256-col chunk of Ua.
// Tail: gk(84)+Co(28) on lanes tx<28.
// ---------------------------------------------------------------------------
__global__ void __launch_bounds__(256, 5)
prologue_kernel(const float* __restrict__ x,
                const float* __restrict__ Ua,
                const float* __restrict__ gk,
                const float* __restrict__ Co,
                const float* __restrict__ Ba2,
                const float* __restrict__ gbias)
{
    __shared__ float xs[16 * D_];           // 32 KB (row 15 zero pad)
    const int b   = blockIdx.x;
    const int rc  = blockIdx.y;
    const int tid = threadIdx.x;
    const int tx  = tid & 31;
    const int ty  = tid >> 5;
    const int row0 = rc * 15;

    // stage 15 rows of x[b]
    const float4* xb = reinterpret_cast<const float4*>(x + (long)b * T_ * D_ + row0 * D_);
    float4* xs4 = reinterpret_cast<float4*>(xs);
    for (int i = tid; i < 15 * (D_/4); i += 256) xs4[i] = xb[i];
    for (int i = tid; i < (D_/4); i += 256) xs4[15 * (D_/4) + i] = make_float4(0.f,0.f,0.f,0.f);
    __syncthreads();

    const int r0 = 2 * ty;
    const int r1 = 2 * ty + 1;
    float* outb = g_scr + (long)b * PT + row0 * NC;
    const float* xr0 = &xs[r0 * D_];
    const float* xr1 = &xs[r1 * D_];

    // ---- Ua, two 256-col chunks ----
    #pragma unroll
    for (int cc = 0; cc < 2; cc++) {
        const int col = cc * 256 + 4 * tx;
        float a0[8], a1[8];
        {
            float4 bA = *reinterpret_cast<const float4*>(&Ba2[col]);
            float4 bB = *reinterpret_cast<const float4*>(&Ba2[col + 128]);
            a0[0]=bA.x; a0[1]=bA.y; a0[2]=bA.z; a0[3]=bA.w;
            a0[4]=bB.x; a0[5]=bB.y; a0[6]=bB.z; a0[7]=bB.w;
            #pragma unroll
            for (int j = 0; j < 8; j++) a1[j] = a0[j];
        }
        #pragma unroll 4
        for (int k = 0; k < D_; k++) {
            float4 w0 = *reinterpret_cast<const float4*>(&Ua[k * D_ + col]);
            float4 w1 = *reinterpret_cast<const float4*>(&Ua[k * D_ + col + 128]);
            float x0 = xr0[k];
            float x1 = xr1[k];
            a0[0] = fmaf(x0, w0.x, a0[0]);
            a0[1] = fmaf(x0, w0.y, a0[1]);
            a0[2] = fmaf(x0, w0.z, a0[2]);
            a0[3] = fmaf(x0, w0.w, a0[3]);
            a0[4] = fmaf(x0, w1.x, a0[4]);
            a0[5] = fmaf(x0, w1.y, a0[5]);
            a0[6] = fmaf(x0, w1.z, a0[6]);
            a0[7] = fmaf(x0, w1.w, a0[7]);
            a1[0] = fmaf(x1, w0.x, a1[0]);
            a1[1] = fmaf(x1, w0.y, a1[1]);
            a1[2] = fmaf(x1, w0.z, a1[2]);
            a1[3] = fmaf(x1, w0.w, a1[3]);
            a1[4] = fmaf(x1, w1.x, a1[4]);
            a1[5] = fmaf(x1, w1.y, a1[5]);
            a1[6] = fmaf(x1, w1.z, a1[6]);
            a1[7] = fmaf(x1, w1.w, a1[7]);
        }
        *reinterpret_cast<float4*>(&outb[r0 * NC + col])       = make_float4(a0[0],a0[1],a0[2],a0[3]);
        *reinterpret_cast<float4*>(&outb[r0 * NC + col + 128]) = make_float4(a0[4],a0[5],a0[6],a0[7]);
        if (r1 < 15) {
            *reinterpret_cast<float4*>(&outb[r1 * NC + col])       = make_float4(a1[0],a1[1],a1[2],a1[3]);
            *reinterpret_cast<float4*>(&outb[r1 * NC + col + 128]) = make_float4(a1[4],a1[5],a1[6],a1[7]);
        }
    }

    // ---- gk (84) + Co (28) on lanes tx<28 ----
    if (tx < 28) {
        const bool isgk  = (tx < 21);
        const float* W   = isgk ? gk : Co;
        const int stride = isgk ? 84 : 28;
        const int col    = isgk ? 4 * tx : 4 * (tx - 21);
        const int ocol   = isgk ? 512 + col : 596 + col;
        float a0[4], a1[4];
        if (isgk) {
            float4 bA = *reinterpret_cast<const float4*>(&gbias[col]);
            a0[0]=bA.x; a0[1]=bA.y; a0[2]=bA.z; a0[3]=bA.w;
        } else {
            a0[0]=0.f; a0[1]=0.f; a0[2]=0.f; a0[3]=0.f;
        }
        #pragma unroll
        for (int j = 0; j < 4; j++) a1[j] = a0[j];
        #pragma unroll 4
        for (int k = 0; k < D_; k++) {
            float4 w = *reinterpret_cast<const float4*>(&W[k * stride + col]);
            float x0 = xr0[k];
            float x1 = xr1[k];
            a0[0] = fmaf(x0, w.x, a0[0]);
            a0[1] = fmaf(x0, w.y, a0[1]);
            a0[2] = fmaf(x0, w.z, a0[2]);
            a0[3] = fmaf(x0, w.w, a0[3]);
            a1[0] = fmaf(x1, w.x, a1[0]);
            a1[1] = fmaf(x1, w.y, a1[1]);
            a1[2] = fmaf(x1, w.z, a1[2]);
            a1[3] = fmaf(x1, w.w, a1[3]);
        }
        *reinterpret_cast<float4*>(&outb[r0 * NC + ocol]) = make_float4(a0[0],a0[1],a0[2],a0[3]);
        if (r1 < 15)
            *reinterpret_cast<float4*>(&outb[r1 * NC + ocol]) = make_float4(a1[0],a1[1],a1[2],a1[3]);
    }
}

// ---------------------------------------------------------------------------
// Recurrence kernel (== R4 known-good): 128 CTAs x 576 threads, 227712 B smem.
// Phase B uses conflict-free stride-32 scalar LDS (lane + 32*i).
// ---------------------------------------------------------------------------
#define SMEM_FLOATS 56928
#define NTH 576

__global__ void __launch_bounds__(NTH)
recur_kernel(const float* __restrict__ Wa,
             const float* __restrict__ Va,
             const float* __restrict__ Ba1,
             const float* __restrict__ grk,
             const float* __restrict__ gbias,
             const float* __restrict__ Wo,
             const float* __restrict__ Uo,
             const float* __restrict__ Bo,
             const float* __restrict__ emb,
             float* __restrict__ out)
{
    extern __shared__ float smem[];
    float*        uah  = smem;                 // [75][512]
    float*        xgc  = smem + 38400;         // [75][112]
    unsigned int* wab  = reinterpret_cast<unsigned int*>(smem + 46800); // [28][256] bf16x2
    float*        va_s = smem + 53968;
    float*        ba1_s= smem + 54480;
    float*        uo_s = smem + 54992;
    float*        was_s= smem + 55776;
    float*        sc_s = smem + 56288;
    float*        xmc_s= smem + 56448;
    float*        hm_s = smem + 56560;
    float*        st_s = smem + 56648;
    float*        pr_s = smem + 56680;
    float*        woy_s= smem + 56712;
    float*        uoh_s= smem + 56744;
    float*        lut_s= smem + 56776;
    float*        b1_s = smem + 56808;
    float*        bo_s = smem + 56896;

    const int tid  = threadIdx.x;
    const int b    = blockIdx.x;
    const int lane = tid & 31;
    const int wid  = tid >> 5;

    // ---- bulk load precomputed UaH / XGC from scratch ----
    const float4* src = reinterpret_cast<const float4*>(g_scr + (long)b * PT);
    for (int i = tid; i < PT/4; i += NTH) {
        float4 v = src[i];
        int base = i * 4;
        int t = base / NC;
        int c = base - t * NC;
        float* dst = (c < 512) ? &uah[t * 512 + c] : &xgc[t * 112 + (c - 512)];
        *reinterpret_cast<float4*>(dst) = v;
    }
    // ---- params ----
    for (int i = tid; i < 512; i += NTH) { va_s[i] = Va[i]; ba1_s[i] = Ba1[i]; }
    for (int i = tid; i < 784; i += NTH) uo_s[i] = Uo[i];
    for (int i = tid; i < 28*256; i += NTH) {
        int r = i >> 8, c = i & 255;
        __nv_bfloat162 h;
        h.x = __float2bfloat16_rn(Wa[r * 512 + 2*c]);
        h.y = __float2bfloat16_rn(Wa[r * 512 + 2*c + 1]);
        wab[i] = *reinterpret_cast<unsigned int*>(&h);
    }
    if (tid < 84) b1_s[tid] = gbias[84 + tid];
    if (tid < 28) {
        bo_s[tid] = Bo[tid];
        float a = 0.0f;
        #pragma unroll
        for (int j = 0; j < 28; j++) a = fmaf(emb[tid * 28 + j], Wo[j], a);
        lut_s[tid] = a;
    }
    if (tid < 32) { st_s[tid] = 0.0f; pr_s[tid] = 0.0f; }
    __syncthreads();

    float va_r[16];
    #pragma unroll
    for (int i = 0; i < 16; i++) va_r[i] = va_s[lane + 32*i];

    float* outb = out + (long)b * T_ * V_;

    for (int t = 0; t < T_; t++) {
        // ---------- Phase A: state-only GEMVs, all in parallel ----------
        if (tid < 256) {
            float2 a = *reinterpret_cast<const float2*>(&ba1_s[2*tid]);
            #pragma unroll
            for (int v = 0; v < 28; v++) {
                float s = st_s[v];
                unsigned int w = wab[v * 256 + tid];
                float wx = __int_as_float(w << 16);
                float wy = __int_as_float(w & 0xffff0000u);
                a.x = fmaf(s, wx, a.x);
                a.y = fmaf(s, wy, a.y);
            }
            *reinterpret_cast<float2*>(&was_s[2*tid]) = a;
        } else if (tid < 340) {
            int g = tid - 256;              // hm: 84 outputs
            float a = b1_s[g];
            #pragma unroll
            for (int v = 0; v < 28; v++) a = fmaf(st_s[v], grk[v * 84 + g], a);
            hm_s[g] = a;
        } else if (wid == 11) {
            if (lane < 28) {                // uoh
                float a = 0.0f;
                #pragma unroll
                for (int u = 0; u < 28; u++) a = fmaf(st_s[u], uo_s[u * 28 + lane], a);
                uoh_s[lane] = a;
            }
        } else if (wid == 12) {
            if (lane < 28) {                // woy (embedding LUT on int(prev_pred))
                int ix = (int)pr_s[lane];
                ix = max(0, min(27, ix));
                woy_s[lane] = lut_s[ix];
            }
        }
        __syncthreads();

        // ---------- Phase B: scores, 18 warps, tanh.approx ----------
        {
            float ws_r[16];
            #pragma unroll
            for (int i = 0; i < 16; i++) ws_r[i] = was_s[lane + 32*i];

            for (int r = wid; r < T_; r += 18) {
                const float* up = &uah[r * 512];
                float acc0 = 0.0f, acc1 = 0.0f;
                #pragma unroll
                for (int i = 0; i < 16; i += 2) {
                    float th0 = tanhf_hw(up[lane + 32*i]     + ws_r[i]);
                    float th1 = tanhf_hw(up[lane + 32*(i+1)] + ws_r[i+1]);
                    acc0 = fmaf(th0, va_r[i],   acc0);
                    acc1 = fmaf(th1, va_r[i+1], acc1);
                }
                float acc = acc0 + acc1;
                #pragma unroll
                for (int o = 16; o; o >>= 1) acc += __shfl_xor_sync(0xffffffffu, acc, o);
                if (lane == 0) sc_s[r] = acc;
            }
        }
        __syncthreads();

        // ---------- Phase C: softmax-in-registers + sm.XGC (warps 0-3) ----------
        if (wid < 4) {
            float s0 = sc_s[lane];
            float s1 = sc_s[lane + 32];
            float s2 = (lane < 11) ? sc_s[lane + 64] : -3.0e38f;
            float m = fmaxf(fmaxf(s0, s1), s2);
            #pragma unroll
            for (int o = 16; o; o >>= 1) m = fmaxf(m, __shfl_xor_sync(0xffffffffu, m, o));
            float e0 = ex2f((s0 - m) * L2E);
            float e1 = ex2f((s1 - m) * L2E);
            float e2 = (lane < 11) ? ex2f((s2 - m) * L2E) : 0.0f;
            float sum = e0 + e1 + e2;
            #pragma unroll
            for (int o = 16; o; o >>= 1) sum += __shfl_xor_sync(0xffffffffu, sum, o);
            float inv = rcpf(sum);

            int c = wid * 28 + ((lane < 28) ? lane : 0);   // 112 cols; lanes 28-31 duplicate
            float a0 = 0.0f, a1 = 0.0f, a2 = 0.0f, a3 = 0.0f;
            #pragma unroll
            for (int k = 0; k < 75; k += 4) {
                float w0 = __shfl_sync(0xffffffffu, (k      < 32) ? e0 : ((k      < 64) ? e1 : e2), k      & 31);
                a0 = fmaf(w0, xgc[k * 112 + c], a0);
                if (k + 1 < 75) {
                    float w1 = __shfl_sync(0xffffffffu, (k+1 < 32) ? e0 : ((k+1 < 64) ? e1 : e2), (k+1) & 31);
                    a1 = fmaf(w1, xgc[(k+1) * 112 + c], a1);
                }
                if (k + 2 < 75) {
                    float w2 = __shfl_sync(0xffffffffu, (k+2 < 32) ? e0 : ((k+2 < 64) ? e1 : e2), (k+2) & 31);
                    a2 = fmaf(w2, xgc[(k+2) * 112 + c], a2);
                }
                if (k + 3 < 75) {
                    float w3 = __shfl_sync(0xffffffffu, (k+3 < 32) ? e0 : ((k+3 < 64) ? e1 : e2), (k+3) & 31);
                    a3 = fmaf(w3, xgc[(k+3) * 112 + c], a3);
                }
            }
            if (lane < 28) xmc_s[c] = ((a0 + a1) + (a2 + a3)) * inv;
        }
        __syncthreads();

        // ---------- Phase D: GRU gates + output softmax (warp 0) ----------
        if (wid == 0) {
            int v = lane;
            float logit = -3.0e38f;
            float ns = 0.0f;
            if (v < 28) {
                float xz = xmc_s[v],      xr = xmc_s[28 + v], xh  = xmc_s[56 + v];
                float hz = hm_s[v],       hr = hm_s[28 + v],  hh_ = hm_s[56 + v];
                float z  = fast_sig(xz + hz);
                float r  = fast_sig(xr + hr);
                float hh = tanhf_hw(fmaf(r, hh_, xh));
                float st = st_s[v];
                ns = fmaf(z, st - hh, hh);
                logit = ((woy_s[v] + uoh_s[v]) + (xmc_s[84 + v] + bo_s[v]));
            }
            float m = logit;
            #pragma unroll
            for (int o = 16; o; o >>= 1) m = fmaxf(m, __shfl_xor_sync(0xffffffffu, m, o));
            float e = (v < 28) ? ex2f((logit - m) * L2E) : 0.0f;
            float sum = e;
            #pragma unroll
            for (int o = 16; o; o >>= 1) sum += __shfl_xor_sync(0xffffffffu, sum, o);
            float p = e * rcpf(sum);
            if (v < 28) {
                st_s[v] = ns;
                pr_s[v] = p;
                outb[t * V_ + v] = p;
            }
        }
        __syncthreads();
    }
}

// ---------------------------------------------------------------------------
extern "C" void kernel_launch(void* const* d_in, const int* in_sizes, int n_in,
                              void* d_out, int out_size)
{
    const float* x    = (const float*)d_in[0];
    const float* Wa   = (const float*)d_in[1];
    const float* Ua   = (const float*)d_in[2];
    const float* Va   = (const float*)d_in[3];
    const float* Ba1  = (const float*)d_in[4];
    const float* Ba2  = (const float*)d_in[5];
    /* Ba3 (d_in[6]) is softmax-invariant: skipped */
    const float* gk   = (const float*)d_in[7];
    const float* grk  = (const float*)d_in[8];
    const float* gb   = (const float*)d_in[9];
    const float* Wo   = (const float*)d_in[10];
    const float* Uo   = (const float*)d_in[11];
    const float* Co   = (const float*)d_in[12];
    const float* Bo   = (const float*)d_in[13];
    const float* emb  = (const float*)d_in[14];
    float* out = (float*)d_out;

    cudaFuncSetAttribute(recur_kernel, cudaFuncAttributeMaxDynamicSharedMemorySize, SMEM_FLOATS * 4);

    dim3 pg(B_, 5);
    prologue_kernel<<<pg, 256>>>(x, Ua, gk, Co, Ba2, gb);
    recur_kernel<<<B_, NTH, SMEM_FLOATS * 4>>>(Wa, Va, Ba1, grk, gb, Wo, Uo, Bo, emb, out);
}